// round 12
// baseline (speedup 1.0000x reference)
#include <cuda_runtime.h>
#include <cuda_fp16.h>
#include <stdint.h>

#define HASH_MASK ((1u << 19) - 1u)
#define RES 128.0f
#define P1 2654435761u
#define P2 805459861u

#define GD 128
// octo fp16 grid: entry(fx,fy,fz) = 8 packed half2 words:
// [ quad(fx):  v(y,z), v(y,z+1), v(y+1,z), v(y+1,z+1);  quad(fx+1): same ]
// 32 B per entry, 32B-aligned -> one L2 sector per point. 67 MB.
__device__ __align__(32) uint32_t g_octo[GD * GD * GD * 8];

__device__ __forceinline__ float2 up2(uint32_t u) {
    __half2 h = *reinterpret_cast<__half2*>(&u);
    return __half22float2(h);
}

// 256-bit gather with L2 evict_last: keep the grid resident in L2.
__device__ __forceinline__ void ld_octo(const uint32_t* p, uint32_t r[8]) {
    asm("ld.global.nc.L2::evict_last.v8.b32 {%0,%1,%2,%3,%4,%5,%6,%7}, [%8];"
        : "=r"(r[0]), "=r"(r[1]), "=r"(r[2]), "=r"(r[3]),
          "=r"(r[4]), "=r"(r[5]), "=r"(r[6]), "=r"(r[7])
        : "l"(p));
}

// 256-bit store with L2 evict_last: grid lines enter L2 at high priority.
__device__ __forceinline__ void st_octo(uint32_t* p, uint32_t w0, uint32_t w1,
                                        uint32_t w2, uint32_t w3, uint32_t w4,
                                        uint32_t w5, uint32_t w6, uint32_t w7) {
    asm volatile("st.global.L2::evict_last.v8.b32 [%0], {%1,%2,%3,%4,%5,%6,%7,%8};"
                 :: "l"(p), "r"(w0), "r"(w1), "r"(w2), "r"(w3),
                    "r"(w4), "r"(w5), "r"(w6), "r"(w7) : "memory");
}

// ---------------- Pass 1: densify (XOR-window gathers, MLP-unrolled) ----------------
#define TY 4
#define TZ 8
#define NROWS ((TY + 1) * (TZ + 1))   // 45
#define SROW 133                      // padded stride vs bank conflicts

__global__ void __launch_bounds__(256) densify_kernel(const float2* __restrict__ ht)
{
    int by = (blockIdx.x >> 4) * TY;   // 32 y-tiles
    int bz = (blockIdx.x & 15) * TZ;   // 16 z-tiles

    __shared__ uint32_t s[NROWS * SROW];

    int tid = threadIdx.x;
    int warp = tid >> 5;
    int lane = tid & 31;

    // Gather phase: all 4 XOR-window loads (+ straggler) in flight before STS.
    for (int r = warp; r < NROWS; r += 8) {
        int yl = r / (TZ + 1);
        int zl = r - yl * (TZ + 1);
        uint32_t base = ((uint32_t)(by + yl) * P1) ^ ((uint32_t)(bz + zl) * P2);

        float2 v0 = __ldg(&ht[(base ^ (uint32_t)(lane      )) & HASH_MASK]);
        float2 v1 = __ldg(&ht[(base ^ (uint32_t)(lane + 32 )) & HASH_MASK]);
        float2 v2 = __ldg(&ht[(base ^ (uint32_t)(lane + 64 )) & HASH_MASK]);
        float2 v3 = __ldg(&ht[(base ^ (uint32_t)(lane + 96 )) & HASH_MASK]);
        float2 v4 = __ldg(&ht[(base ^ 128u) & HASH_MASK]);

        __half2 h0 = __floats2half2_rn(v0.x, v0.y);
        __half2 h1 = __floats2half2_rn(v1.x, v1.y);
        __half2 h2 = __floats2half2_rn(v2.x, v2.y);
        __half2 h3 = __floats2half2_rn(v3.x, v3.y);
        uint32_t* row = &s[r * SROW];
        row[lane      ] = *reinterpret_cast<uint32_t*>(&h0);
        row[lane + 32 ] = *reinterpret_cast<uint32_t*>(&h1);
        row[lane + 64 ] = *reinterpret_cast<uint32_t*>(&h2);
        row[lane + 96 ] = *reinterpret_cast<uint32_t*>(&h3);
        if (lane == 0) {
            __half2 h4 = __floats2half2_rn(v4.x, v4.y);
            row[128] = *reinterpret_cast<uint32_t*>(&h4);
        }
    }
    __syncthreads();

    // Store phase: 32B octo entries, coalesced v8 stores, evict_last.
    for (int e = tid; e < GD * TY * TZ; e += 256) {
        int ix = e >> 5;
        int q  = e & 31;
        int yl = q >> 3;
        int zl = q & 7;
        int r = yl * (TZ + 1) + zl;
        uint32_t w0 = s[r * SROW + ix];
        uint32_t w1 = s[(r + 1) * SROW + ix];
        uint32_t w2 = s[(r + TZ + 1) * SROW + ix];
        uint32_t w3 = s[(r + TZ + 2) * SROW + ix];
        uint32_t w4 = s[r * SROW + ix + 1];
        uint32_t w5 = s[(r + 1) * SROW + ix + 1];
        uint32_t w6 = s[(r + TZ + 1) * SROW + ix + 1];
        uint32_t w7 = s[(r + TZ + 2) * SROW + ix + 1];
        uint32_t* dst = &g_octo[(((ix * GD) + by + yl) * GD + bz + zl) * 8];
        st_octo(dst, w0, w1, w2, w3, w4, w5, w6, w7);
    }
}

// ---------------- Pass 2: trilinear interp, 2 pts/thread, 1 LDG.256/pt ----------------
__device__ __forceinline__ void lerp8(
    const uint32_t w[8], float dx, float dy, float dz, float& oa, float& ob)
{
    float2 v000 = up2(w[0]), v001 = up2(w[1]), v010 = up2(w[2]), v011 = up2(w[3]);
    float2 v100 = up2(w[4]), v101 = up2(w[5]), v110 = up2(w[6]), v111 = up2(w[7]);

    float omx = 1.0f - dx, omy = 1.0f - dy, omz = 1.0f - dz;

    float c00a = v000.x * omx + v100.x * dx;
    float c00b = v000.y * omx + v100.y * dx;
    float c01a = v001.x * omx + v101.x * dx;
    float c01b = v001.y * omx + v101.y * dx;
    float c10a = v010.x * omx + v110.x * dx;
    float c10b = v010.y * omx + v110.y * dx;
    float c11a = v011.x * omx + v111.x * dx;
    float c11b = v011.y * omx + v111.y * dx;

    float c0a = c00a * omy + c10a * dy;
    float c0b = c00b * omy + c10b * dy;
    float c1a = c01a * omy + c11a * dy;
    float c1b = c01b * omy + c11b * dy;

    oa = c0a * omz + c1a * dz;
    ob = c0b * omz + c1b * dz;
}

__global__ void __launch_bounds__(256) ngp_interp_kernel(
    const float* __restrict__ x,
    float2* __restrict__ out,
    int n)
{
    int t = blockIdx.x * blockDim.x + threadIdx.x;
    int i0 = t * 2;
    if (i0 >= n) return;

    const float2* __restrict__ x2 = (const float2*)x;
    float2 a = __ldcs(&x2[3 * t + 0]);
    float2 b = __ldcs(&x2[3 * t + 1]);
    float2 c = __ldcs(&x2[3 * t + 2]);

    float sx0 = a.x * RES, sy0 = a.y * RES, sz0 = b.x * RES;
    float fx0 = floorf(sx0), fy0 = floorf(sy0), fz0 = floorf(sz0);
    int b0 = ((int)fx0 * GD + (int)fy0) * GD + (int)fz0;

    float sx1 = b.y * RES, sy1 = c.x * RES, sz1 = c.y * RES;
    float fx1 = floorf(sx1), fy1 = floorf(sy1), fz1 = floorf(sz1);
    int b1 = ((int)fx1 * GD + (int)fy1) * GD + (int)fz1;

    uint32_t w0[8], w1[8];
    ld_octo(&g_octo[b0 * 8], w0);
    ld_octo(&g_octo[b1 * 8], w1);

    float o0a, o0b, o1a, o1b;
    lerp8(w0, sx0 - fx0, sy0 - fy0, sz0 - fz0, o0a, o0b);
    lerp8(w1, sx1 - fx1, sy1 - fy1, sz1 - fz1, o1a, o1b);

    if (i0 + 1 < n) {
        float4* __restrict__ out4 = (float4*)out;
        __stcs(&out4[t], make_float4(o0a, o0b, o1a, o1b));
    } else {
        __stcs(&out[i0], make_float2(o0a, o0b));
    }
}

extern "C" void kernel_launch(void* const* d_in, const int* in_sizes, int n_in,
                              void* d_out, int out_size) {
    const float* x = (const float*)d_in[0];
    const float2* ht = (const float2*)d_in[1];
    float2* out = (float2*)d_out;
    int n = in_sizes[0] / 3;

    densify_kernel<<<512, 256>>>(ht);

    int threads = 256;
    int pts_per_block = threads * 2;
    int blocks = (n + pts_per_block - 1) / pts_per_block;
    ngp_interp_kernel<<<blocks, threads>>>(x, out, n);
}